// round 10
// baseline (speedup 1.0000x reference)
#include <cuda_runtime.h>
#include <cuda_bf16.h>
#include <cuda_fp16.h>
#include <cstdint>
#include <cstddef>

// ---------------- problem constants ----------------------------------------
#define BB 256
#define SS 256
#define EE 384
#define HH 6
#define DH 64
#define FF 1536
#define MM (BB*SS)                  // 65536
#define BHSD ((size_t)BB*HH*SS*DH)  // 25,165,824

// ---------------- scratch (device globals; no allocation allowed) ----------
__device__ __half  g_hln[(size_t)MM*EE];   // LN1 out fp16
__device__ __half  g_qkv[3*BHSD];          // q,k,v fp16 [3][B,H,S,D]
__device__ __half  g_o[(size_t)MM*EE];     // attention out fp16
__device__ float   g_x1[(size_t)MM*EE];    // x + proj (fp32)
__device__ __half  g_h2[(size_t)MM*EE];    // LN2 out fp16
__device__ __half  g_mid[(size_t)MM*FF];   // relu(ffn1) fp16
__device__ __half  g_wqkv[(size_t)1152*384];
__device__ __half  g_wp[(size_t)384*384];
__device__ __half  g_w1[(size_t)1536*384];
__device__ __half  g_w2[(size_t)384*1536];

// ---------------- helpers ---------------------------------------------------
__device__ __forceinline__ uint32_t smem_to_u32(const void* p) {
    uint32_t a;
    asm("{ .reg .u64 t; cvta.to.shared.u64 t, %1; cvt.u32.u64 %0, t; }"
        : "=r"(a) : "l"(p));
    return a;
}

#define CP_ASYNC16(sm, gp) \
    asm volatile("cp.async.cg.shared.global [%0], [%1], 16;" \
        :: "r"((uint32_t)(sm)), "l"(gp) : "memory")
#define CP_COMMIT() asm volatile("cp.async.commit_group;" ::: "memory")
#define CP_WAIT1()  asm volatile("cp.async.wait_group 1;" ::: "memory")

__device__ __forceinline__ void ldsm_x4(uint32_t* r, uint32_t addr) {
    asm volatile("ldmatrix.sync.aligned.m8n8.x4.shared.b16 {%0,%1,%2,%3}, [%4];"
        : "=r"(r[0]), "=r"(r[1]), "=r"(r[2]), "=r"(r[3]) : "r"(addr));
}
__device__ __forceinline__ void mma16816(float* d, const uint32_t* a, const uint32_t* b) {
    asm volatile(
        "mma.sync.aligned.m16n8k16.row.col.f32.f16.f16.f32 "
        "{%0,%1,%2,%3}, {%4,%5,%6,%7}, {%8,%9}, {%0,%1,%2,%3};"
        : "+f"(d[0]), "+f"(d[1]), "+f"(d[2]), "+f"(d[3])
        : "r"(a[0]), "r"(a[1]), "r"(a[2]), "r"(a[3]), "r"(b[0]), "r"(b[1]));
}

// ---------------- weight packing (fp16) -------------------------------------
__global__ void pack_qkv_kernel(const float* __restrict__ Wq,
                                const float* __restrict__ Wk,
                                const float* __restrict__ Wv) {
    int idx = blockIdx.x * 256 + threadIdx.x;
    if (idx >= 1152 * 384) return;
    int n = idx / 384, k = idx - n * 384;
    int m3 = n / 384;
    int rem = n - m3 * 384;
    int h = rem >> 6, d = rem & 63;
    const float* W = (m3 == 0) ? Wq : (m3 == 1) ? Wk : Wv;
    g_wqkv[idx] = __float2half(W[((size_t)h * 384 + k) * 64 + d]);
}

// B[n,k] = src[k*ldn + n]
__global__ void pack_gen_kernel(const float* __restrict__ src, __half* dst,
                                int N, int K, int ldn) {
    int idx = blockIdx.x * 256 + threadIdx.x;
    if (idx >= N * K) return;
    int n = idx / K, k = idx - n * K;
    dst[idx] = __float2half(src[(size_t)k * ldn + n]);
}

// ---------------- LayerNorm -> fp16 ----------------------------------------
__global__ void ln_kernel(const float* __restrict__ in,
                          const float* __restrict__ gamma,
                          const float* __restrict__ beta,
                          __half* __restrict__ out) {
    __shared__ float red1[4];
    __shared__ float red2[4];
    int row = blockIdx.x;
    int tid = threadIdx.x;
    const float* r = in + (size_t)row * EE;
    float v0 = r[tid], v1 = r[tid + 128], v2 = r[tid + 256];
    float s = v0 + v1 + v2;
    #pragma unroll
    for (int o = 16; o; o >>= 1) s += __shfl_xor_sync(0xffffffffu, s, o);
    if ((tid & 31) == 0) red1[tid >> 5] = s;
    __syncthreads();
    float mu = (red1[0] + red1[1] + red1[2] + red1[3]) * (1.0f / 384.0f);
    float d0 = v0 - mu, d1 = v1 - mu, d2 = v2 - mu;
    float vs = d0 * d0 + d1 * d1 + d2 * d2;
    #pragma unroll
    for (int o = 16; o; o >>= 1) vs += __shfl_xor_sync(0xffffffffu, vs, o);
    if ((tid & 31) == 0) red2[tid >> 5] = vs;
    __syncthreads();
    float var = (red2[0] + red2[1] + red2[2] + red2[3]) * (1.0f / 384.0f);
    float rstd = rsqrtf(var + 1e-5f);
    __half* w = out + (size_t)row * EE;
    #pragma unroll
    for (int j = 0; j < 3; j++) {
        int c = tid + j * 128;
        float d = (j == 0) ? d0 : (j == 1) ? d1 : d2;
        w[c] = __float2half(d * rstd * gamma[c] + beta[c]);
    }
}

// ---------------- mma.sync GEMM (fp16 in, fp32 accum) ----------------------
// D[M,N] = A[M,K] . B[N,K]^T
// modes: 0 = QKV scatter fp16; 1 = resid + D + bias (fp32);
//        2 = relu(D+bias) -> fp16; 3 = same as 1 (out to d_out)
// Tile: 128x128, BK=64, 3-stage cp.async pipeline, 8 warps, warp tile 64x32.
// Stage: A 128x144B + B 128x144B (128B data + 16B pad; 4r-mod-32 bank-clean).
// Occupancy 2 CTA/SM (216KB smem of 228KB).
#define STAGE_BYTES 36864
#define GSMEM (3 * STAGE_BYTES)

__global__ __launch_bounds__(256, 2)
void mma_gemm(const __half* __restrict__ A, const __half* __restrict__ B,
              void* outp, const float* __restrict__ bias,
              const float* __restrict__ resid, int K, int N, int mode) {
    extern __shared__ __align__(128) uint8_t dsm[];
    const uint32_t sb = smem_to_u32(dsm);
    const int tid = threadIdx.x;
    const int lane = tid & 31;
    const int wid = tid >> 5;
    const int wm = wid >> 2;        // 0..1
    const int wn = wid & 3;         // 0..3
    const int m0 = blockIdx.y * 128;
    const int n0 = blockIdx.x * 128;
    const int CT = K >> 6;          // K chunks of 64

    // per-thread load coords: 4 passes of 16B for A, 4 for B per stage
    const int rr = tid >> 3;        // 0..31 (+32 per pass)
    const int qq = tid & 7;         // 16B column chunk within 128B row

    float acc[4][4][4];
    #pragma unroll
    for (int i = 0; i < 4; i++)
        #pragma unroll
        for (int j = 0; j < 4; j++)
            #pragma unroll
            for (int t = 0; t < 4; t++) acc[i][j][t] = 0.0f;

    #define LOAD_STAGE(c) do { \
        int s_ = (c) % 3; \
        int k0_ = (c) << 6; \
        uint32_t sa_ = sb + s_ * STAGE_BYTES; \
        uint32_t sbm_ = sa_ + 18432u; \
        _Pragma("unroll") \
        for (int i_ = 0; i_ < 4; ++i_) { \
            int r_ = rr + i_ * 32; \
            CP_ASYNC16(sa_  + r_ * 144 + qq * 16, A + (size_t)(m0 + r_) * K + k0_ + qq * 8); \
            CP_ASYNC16(sbm_ + r_ * 144 + qq * 16, B + (size_t)(n0 + r_) * K + k0_ + qq * 8); \
        } \
    } while (0)

    LOAD_STAGE(0); CP_COMMIT();
    LOAD_STAGE(1); CP_COMMIT();

    const uint32_t a_row  = (uint32_t)(wm * 64 + (lane & 15));
    const uint32_t a_coff = (uint32_t)((lane >> 4) * 16);   // 8 halves
    const uint32_t b_row  = (uint32_t)(wn * 32 + (lane & 15));
    const uint32_t b_coff = (uint32_t)((lane >> 4) * 16);

    for (int c = 0; c < CT; ++c) {
        CP_WAIT1();
        __syncthreads();   // stage c resident; stage c-1 LDSM reads done
        if (c + 2 < CT) { LOAD_STAGE(c + 2); }
        CP_COMMIT();
        uint32_t sa = sb + (c % 3) * STAGE_BYTES;
        uint32_t sbm = sa + 18432u;
        #pragma unroll
        for (int ks = 0; ks < 4; ++ks) {
            uint32_t afr[4][4], bq[2][4];
            #pragma unroll
            for (int mt = 0; mt < 4; ++mt)
                ldsm_x4(afr[mt], sa + (a_row + mt * 16) * 144 + ks * 32 + a_coff);
            #pragma unroll
            for (int np = 0; np < 2; ++np)
                ldsm_x4(bq[np], sbm + (b_row + np * 16) * 144 + ks * 32 + b_coff);
            #pragma unroll
            for (int mt = 0; mt < 4; ++mt)
                #pragma unroll
                for (int nt = 0; nt < 4; ++nt) {
                    uint32_t bb[2];
                    bb[0] = bq[nt >> 1][(nt & 1)];
                    bb[1] = bq[nt >> 1][(nt & 1) + 2];
                    mma16816(acc[mt][nt], afr[mt], bb);
                }
        }
        // no trailing barrier: next wait_group+barrier orders buffer reuse
    }

    // ---- epilogue: direct stores ----
    #pragma unroll
    for (int mt = 0; mt < 4; ++mt) {
        #pragma unroll
        for (int nt = 0; nt < 4; ++nt) {
            int col = n0 + wn * 32 + nt * 8 + (lane & 3) * 2;
            #pragma unroll
            for (int half_ = 0; half_ < 2; ++half_) {
                int rg = m0 + wm * 64 + mt * 16 + (lane >> 2) + half_ * 8;
                float v0 = acc[mt][nt][half_ * 2 + 0];
                float v1 = acc[mt][nt][half_ * 2 + 1];
                if (mode == 0) {
                    int m3 = col / 384;
                    int rem = col - m3 * 384;
                    int h = rem >> 6, dd = rem & 63;
                    int b = rg >> 8, sq = rg & 255;
                    __half2 val = __floats2half2_rn(v0, v1);
                    *(__half2*)((__half*)outp + (size_t)m3 * BHSD +
                                ((size_t)((b * HH + h) * SS + sq)) * DH + dd) = val;
                } else if (mode == 2) {
                    float s0 = fmaxf(v0 + bias[col], 0.f);
                    float s1 = fmaxf(v1 + bias[col + 1], 0.f);
                    *(__half2*)((__half*)outp + (size_t)rg * FF + col) =
                        __floats2half2_rn(s0, s1);
                } else {
                    float2 rr2 = *(const float2*)(resid + (size_t)rg * N + col);
                    float2 val = make_float2(v0 + bias[col] + rr2.x,
                                             v1 + bias[col + 1] + rr2.y);
                    *(float2*)((float*)outp + (size_t)rg * N + col) = val;
                }
            }
        }
    }
}

// ---------------- attention: online softmax, fp16 in/out, fp32 math --------
// SMSP-balanced query mapping: warp w -> query block (w<4 ? w : 11-w).
__global__ __launch_bounds__(256, 1)
void attn_kernel() {
    extern __shared__ float attnsm[];
    float* Ksm = attnsm;
    float* Vsm = attnsm + SS * DH;
    int bh = blockIdx.x;
    int b = bh / HH;
    int h = bh - b * HH;
    int tid = threadIdx.x;
    int lane = tid & 31;
    int wid = tid >> 5;

    const __half* qb = g_qkv + (size_t)bh * SS * DH;
    const __half* kb = g_qkv + BHSD + (size_t)bh * SS * DH;
    const __half* vb = g_qkv + 2 * BHSD + (size_t)bh * SS * DH;

    // load K,V (fp16 global) -> fp32 smem
    const uint4* k8 = (const uint4*)kb;   // 8 halves per uint4
    const uint4* v8 = (const uint4*)vb;
    #pragma unroll
    for (int i = 0; i < (SS * DH / 8) / 256; i++) {
        int idx = tid + i * 256;
        uint4 kk = k8[idx];
        uint4 vv = v8[idx];
        const __half2* kp = (const __half2*)&kk;
        const __half2* vp = (const __half2*)&vv;
        #pragma unroll
        for (int j = 0; j < 4; j++) {
            float2 kf = __half22float2(kp[j]);
            float2 vf = __half22float2(vp[j]);
            Ksm[idx * 8 + j * 2 + 0] = kf.x;
            Ksm[idx * 8 + j * 2 + 1] = kf.y;
            Vsm[idx * 8 + j * 2 + 0] = vf.x;
            Vsm[idx * 8 + j * 2 + 1] = vf.y;
        }
    }
    __syncthreads();

    int qblk = (wid < 4) ? wid : 11 - wid;
    int s = qblk * 32 + lane;
    float4 q[16];
    {
        const uint4* qr = (const uint4*)(qb + (size_t)s * DH);
        #pragma unroll
        for (int i = 0; i < 8; i++) {
            uint4 qq = qr[i];
            const __half2* qp = (const __half2*)&qq;
            float2 f0 = __half22float2(qp[0]);
            float2 f1 = __half22float2(qp[1]);
            float2 f2 = __half22float2(qp[2]);
            float2 f3 = __half22float2(qp[3]);
            q[i * 2 + 0] = make_float4(f0.x, f0.y, f1.x, f1.y);
            q[i * 2 + 1] = make_float4(f2.x, f2.y, f3.x, f3.y);
        }
    }

    const float scale = 0.125f;
    float mx = -1e30f, sum = 0.0f;
    float4 o[16];
    #pragma unroll
    for (int i = 0; i < 16; i++) o[i] = make_float4(0.f, 0.f, 0.f, 0.f);

    for (int t = 0; t <= s; t++) {
        const float4* kr = (const float4*)(Ksm + t * DH);
        float acc = 0.0f;
        #pragma unroll
        for (int i = 0; i < 16; i++) {
            float4 kk = kr[i];
            acc = fmaf(q[i].x, kk.x, acc);
            acc = fmaf(q[i].y, kk.y, acc);
            acc = fmaf(q[i].z, kk.z, acc);
            acc = fmaf(q[i].w, kk.w, acc);
        }
        float sc = acc * scale;
        float p;
        if (sc > mx) {
            float corr = __expf(mx - sc);
            sum *= corr;
            #pragma unroll
            for (int i = 0; i < 16; i++) {
                o[i].x *= corr; o[i].y *= corr; o[i].z *= corr; o[i].w *= corr;
            }
            mx = sc;
            p = 1.0f;
        } else {
            p = __expf(sc - mx);
        }
        sum += p;
        const float4* vr = (const float4*)(Vsm + t * DH);
        #pragma unroll
        for (int i = 0; i < 16; i++) {
            float4 vv = vr[i];
            o[i].x = fmaf(p, vv.x, o[i].x);
            o[i].y = fmaf(p, vv.y, o[i].y);
            o[i].z = fmaf(p, vv.z, o[i].z);
            o[i].w = fmaf(p, vv.w, o[i].w);
        }
    }
    float inv = 1.0f / sum;
    __half* ow = g_o + (size_t)(b * SS + s) * EE + h * DH;
    #pragma unroll
    for (int i = 0; i < 16; i++) {
        *(__half2*)(ow + i * 4 + 0) = __floats2half2_rn(o[i].x * inv, o[i].y * inv);
        *(__half2*)(ow + i * 4 + 2) = __floats2half2_rn(o[i].z * inv, o[i].w * inv);
    }
}

// ---------------- host -----------------------------------------------------
extern "C" void kernel_launch(void* const* d_in, const int* in_sizes, int n_in,
                              void* d_out, int out_size) {
    const float* x   = (const float*)d_in[0];
    const float* Wq  = (const float*)d_in[1];
    const float* Wk  = (const float*)d_in[2];
    const float* Wv  = (const float*)d_in[3];
    const float* Wp  = (const float*)d_in[4];
    const float* bp  = (const float*)d_in[5];
    const float* W1  = (const float*)d_in[6];
    const float* b1  = (const float*)d_in[7];
    const float* W2  = (const float*)d_in[8];
    const float* b2  = (const float*)d_in[9];
    const float* g1  = (const float*)d_in[10];
    const float* be1 = (const float*)d_in[11];
    const float* g2  = (const float*)d_in[12];
    const float* be2 = (const float*)d_in[13];
    float* out = (float*)d_out;

    void *hlnv, *qkvv, *ov, *x1v, *h2v, *midv, *wqkvv, *wpv, *w1v, *w2v;
    cudaGetSymbolAddress(&hlnv,  g_hln);
    cudaGetSymbolAddress(&qkvv,  g_qkv);
    cudaGetSymbolAddress(&ov,    g_o);
    cudaGetSymbolAddress(&x1v,   g_x1);
    cudaGetSymbolAddress(&h2v,   g_h2);
    cudaGetSymbolAddress(&midv,  g_mid);
    cudaGetSymbolAddress(&wqkvv, g_wqkv);
    cudaGetSymbolAddress(&wpv,   g_wp);
    cudaGetSymbolAddress(&w1v,   g_w1);
    cudaGetSymbolAddress(&w2v,   g_w2);

    __half* hln  = (__half*)hlnv;
    __half* qkv  = (__half*)qkvv;
    __half* o    = (__half*)ov;
    float*  x1   = (float*)x1v;
    __half* h2   = (__half*)h2v;
    __half* mid  = (__half*)midv;
    __half* wqkv = (__half*)wqkvv;
    __half* wp   = (__half*)wpv;
    __half* w1   = (__half*)w1v;
    __half* w2   = (__half*)w2v;

    cudaFuncSetAttribute(mma_gemm, cudaFuncAttributeMaxDynamicSharedMemorySize, GSMEM);
    cudaFuncSetAttribute(attn_kernel, cudaFuncAttributeMaxDynamicSharedMemorySize,
                         2 * SS * DH * (int)sizeof(float));

    // weight packing (fp16)
    pack_qkv_kernel<<<(1152 * 384 + 255) / 256, 256>>>(Wq, Wk, Wv);
    pack_gen_kernel<<<(384 * 384 + 255) / 256, 256>>>(Wp, wp, 384, 384, 384);
    pack_gen_kernel<<<(1536 * 384 + 255) / 256, 256>>>(W1, w1, 1536, 384, 1536);
    pack_gen_kernel<<<(384 * 1536 + 255) / 256, 256>>>(W2, w2, 384, 1536, 384);
    // LN1
    ln_kernel<<<MM, 128>>>(x, g1, be1, hln);
    // QKV projection (scatter into [3][B,H,S,D] fp16)
    mma_gemm<<<dim3(9, 512), 256, GSMEM>>>(
        hln, wqkv, qkv, nullptr, nullptr, 384, 1152, 0);
    // causal attention
    attn_kernel<<<BB * HH, 256, 2 * SS * DH * sizeof(float)>>>();
    // out projection + residual: x1 = x + o@Wp + bp
    mma_gemm<<<dim3(3, 512), 256, GSMEM>>>(
        o, wp, x1, bp, x, 384, 384, 1);
    // LN2
    ln_kernel<<<MM, 128>>>(x1, g2, be2, h2);
    // FFN1 + relu -> fp16
    mma_gemm<<<dim3(12, 512), 256, GSMEM>>>(
        h2, w1, mid, b1, nullptr, 384, 1536, 2);
    // FFN2 + residual -> out
    mma_gemm<<<dim3(3, 512), 256, GSMEM>>>(
        mid, w2, out, b2, x1, 1536, 384, 3);
}